// round 5
// baseline (speedup 1.0000x reference)
#include <cuda_runtime.h>

// ProtoLayer (Kendall rank correlation) — fused bit-pack + popcount.
//
// B=4, Q=75, P=5, D=640. n_pairs = 640*639/2 = 204480.
// Pair set (order-free; sign(x_a-x_b)*sign(y_a-y_b) is symmetric in a<->b):
// all unordered pairs at circular distance 1..320, distance-320 half deduped.
// Per-thread packing (thread i, r=i&31, tbase=i&~31):
//   word j (j=0..10), bit m:  x[tbase + j*32 + m] > x[i]       (circular, xs duplicated)
//   word 0 masked to m>r (dist>=1); word 10 masked to m<=r (dist<=320),
//   and for i>=320 bit m==r dropped (dedup of the distance-320 pair).
// Masked slots are 0 in BOTH q and p words -> contribute 0 to popc(xor).
// Ties dropped (continuous gaussian inputs; one tie shifts a result by 1/204480).
//   sum_pairs sq*sp = NPAIRS - 2*popc(Gq ^ Gp)

#define DIM     640
#define BB      4
#define QQ      75
#define PP      5
#define NQ      (BB * QQ)     // 300
#define NP      (BB * PP)     // 20
#define NJ      11            // words per thread
#define NPAIRS  204480

__device__ __align__(16) unsigned g_pbits[NP][NJ * DIM];   // 0.56 MB, L2-resident

// Build the 11 bit-words for thread i from duplicated xs[0..1279].
__device__ __forceinline__ void build_words(const float* __restrict__ xs,
                                            int i, float xi, unsigned w[NJ])
{
    const int r     = i & 31;
    const int tbase = i & ~31;
#pragma unroll
    for (int j = 0; j < NJ; j++) {
        const float4* __restrict__ ch = (const float4*)(xs + tbase + j * 32);
        unsigned wj = 0;
#pragma unroll
        for (int c = 0; c < 8; c++) {
            const float4 v = ch[c];            // LDS.128: 4 targets per load
            wj |= (v.x > xi) ? (1u << (4 * c + 0)) : 0u;
            wj |= (v.y > xi) ? (1u << (4 * c + 1)) : 0u;
            wj |= (v.z > xi) ? (1u << (4 * c + 2)) : 0u;
            wj |= (v.w > xi) ? (1u << (4 * c + 3)) : 0u;
        }
        w[j] = wj;
    }
    w[0]  &= ~((2u << r) - 1u);                               // keep dist >= 1
    w[10] &= (i < 320) ? ((2u << r) - 1u) : ((1u << r) - 1u); // dist <= 320, dedup d=320
}

// grid = 20 (one block per proto vector), block = 640.
__global__ __launch_bounds__(DIM) void proto_build_kernel(const float* __restrict__ pf)
{
    __shared__ __align__(16) float xs[2 * DIM];
    const int vec = blockIdx.x;
    const int i   = threadIdx.x;

    const float xi = pf[(size_t)vec * DIM + i];
    xs[i]       = xi;
    xs[i + DIM] = xi;
    __syncthreads();

    unsigned w[NJ];
    build_words(xs, i, xi, w);
#pragma unroll
    for (int j = 0; j < NJ; j++) g_pbits[vec][j * DIM + i] = w[j];
}

// grid = 300 (one block per (b,q)), block = 640. Builds q-bits in registers,
// streams proto bits from L2, popcounts, reduces.
__global__ __launch_bounds__(DIM, 2) void tau_fused_kernel(const float* __restrict__ qf,
                                                           float* __restrict__ out)
{
    __shared__ __align__(16) float xs[2 * DIM];
    __shared__ int s_part[PP][DIM / 32];       // per-warp partial sums

    const int bq = blockIdx.x;                 // b*QQ + q
    const int b  = bq / QQ;
    const int i  = threadIdx.x;

    const float xi = qf[(size_t)bq * DIM + i];
    xs[i]       = xi;
    xs[i + DIM] = xi;
    __syncthreads();

    unsigned w[NJ];
    build_words(xs, i, xi, w);

    int ds[PP] = {0, 0, 0, 0, 0};
#pragma unroll
    for (int p = 0; p < PP; p++) {
        const unsigned* __restrict__ pb = g_pbits[b * PP + p];
#pragma unroll
        for (int j = 0; j < NJ; j++)
            ds[p] += __popc(w[j] ^ pb[j * DIM + i]);   // coalesced LDG.32
    }

    const int warp = i >> 5;
#pragma unroll
    for (int p = 0; p < PP; p++) {
        int c = ds[p];
#pragma unroll
        for (int o = 16; o; o >>= 1) c += __shfl_down_sync(0xffffffffu, c, o);
        if ((i & 31) == 0) s_part[p][warp] = c;
    }
    __syncthreads();

    if (i < PP) {
        int s = 0;
#pragma unroll
        for (int k = 0; k < DIM / 32; k++) s += s_part[i][k];
        out[bq * PP + i] = (float)(NPAIRS - 2 * s) / (float)NPAIRS;
    }
}

extern "C" void kernel_launch(void* const* d_in, const int* in_sizes, int n_in,
                              void* d_out, int out_size)
{
    const float* qf = (const float*)d_in[0];   // query_feat (4,75,640)
    const float* pf = (const float*)d_in[1];   // proto_feat (4,5,640)
    if (n_in >= 2 && in_sizes[0] < in_sizes[1]) {   // defensive: query is larger
        const float* t = qf; qf = pf; pf = t;
    }

    proto_build_kernel<<<NP, DIM>>>(pf);
    tau_fused_kernel<<<NQ, DIM>>>(qf, (float*)d_out);
}